// round 7
// baseline (speedup 1.0000x reference)
#include <cuda_runtime.h>
#include <cuda_fp16.h>
#include <cstdint>
#include <cstddef>

#define B_   32
#define DIN  64
#define DS   1024
#define L_   2048
#define PP   64      // p per block
#define TC   32      // timesteps per chunk
#define NC   (L_ / TC)
#define S2   35      // stage stride (floats): conflict-free scalar access
#define AS   70      // wsB row stride in halves

// pre-transposed input: g_ut[b][l][h] fp16 (8 MB), written by pre-kernel
__device__ __half g_ut[(size_t)B_ * L_ * DIN];

// dynamic smem: stage[2 par][2 bb][PP][S2] fp32 + wsB[PP][AS] fp16
#define STAGE_BYTES (2 * 2 * PP * S2 * 4)    // 35840
#define WSB_BYTES   (PP * AS * 2)            // 8960
#define SMEM_TOTAL  (STAGE_BYTES + WSB_BYTES)  // 44800 -> 2 CTAs/SM fits

#define BAR_SYNC(id, cnt) asm volatile("bar.sync %0, %1;" :: "r"(id), "r"(cnt) : "memory")

// ---------------------------------------------------------------------------
// Pre-kernel: g_ut[b][l][h] = fp16(u[b][h][l])   (tiled transpose, ~24 MB)
// ---------------------------------------------------------------------------
__global__ __launch_bounds__(256)
void transpose_u(const float* __restrict__ u) {
    __shared__ float ts[DIN][33];
    const int b  = blockIdx.y;
    const int lc = blockIdx.x * 32;
    const int tid = threadIdx.x;
    const float* ub = u + (size_t)b * DIN * L_;

    #pragma unroll
    for (int k = 0; k < 8; k++) {
        int idx = tid + k * 256;          // 0..2047
        int h = idx >> 5, l = idx & 31;
        ts[h][l] = ub[(size_t)h * L_ + lc + l];   // coalesced over l
    }
    __syncthreads();

    const int l  = tid >> 3;              // 0..31
    const int h0 = (tid & 7) * 8;         // 0,8,..,56
    __half2 p[4];
    #pragma unroll
    for (int j = 0; j < 4; j++)
        p[j] = __halves2half2(__float2half_rn(ts[h0 + 2 * j][l]),
                              __float2half_rn(ts[h0 + 2 * j + 1][l]));
    *(uint4*)(g_ut + ((size_t)b * L_ + lc + l) * DIN + h0) = *(uint4*)p;
}

// ---------------------------------------------------------------------------
// Fused kernel: 4 producer warps (fp16 MMA from g_ut + reg-resident B) +
//               4 consumer warps (leaky-tanh chain + coalesced transpose out)
// ---------------------------------------------------------------------------
__global__ __launch_bounds__(256, 2)
void esn_fused(const float* __restrict__ w_in,
               const float* __restrict__ w_hh,
               const float* __restrict__ bias,
               float* __restrict__ out) {
    extern __shared__ unsigned char smem_raw[];
    float*  stage = (float*)smem_raw;                      // [2][2][PP][S2]
    __half* wsB   = (__half*)(smem_raw + STAGE_BYTES);     // [PP][AS]

    const int tid   = threadIdx.x;
    const int p0    = blockIdx.x * PP;
    const int bpair = blockIdx.y;          // b = 2*bpair, 2*bpair+1

    // wsB fill: wsB[p][k] = fp16(w_in[p0+p][k])
    for (int i = tid; i < PP * DIN; i += 256) {
        int p = i >> 6, k = i & 63;
        wsB[p * AS + k] = __float2half_rn(w_in[(size_t)(p0 + p) * DIN + k]);
    }
    __syncthreads();

    if (tid < 128) {
        // ===================== PRODUCERS (4 warps) =========================
        const int w    = tid >> 5;
        const int bw   = w >> 1;             // batch half
        const int wi   = w & 1;              // 32-wide p tile
        const int lane = tid & 31;
        const int g = lane >> 2, t = lane & 3;
        const __half* ut = g_ut + (size_t)(bpair * 2 + bw) * L_ * DIN;

        // chunk-invariant B fragments: 4 kt x 4 n-tiles x 2 regs = 32
        uint32_t bfr[4][4][2];
        #pragma unroll
        for (int kt = 0; kt < 4; kt++)
            #pragma unroll
            for (int in = 0; in < 4; in++) {
                const __half* wp = wsB + (size_t)(wi * 32 + in * 8 + g) * AS + kt * 16 + 2 * t;
                bfr[kt][in][0] = *(const uint32_t*)(wp);
                bfr[kt][in][1] = *(const uint32_t*)(wp + 8);
            }

        for (int it = 0; it <= NC; ++it) {
            if (it < NC) {
                const int par = it & 1;
                const int lc  = it * TC;
                const __half* ua = ut + (size_t)lc * DIN;

                float acc[2][4][4];
                #pragma unroll
                for (int im = 0; im < 2; im++)
                    #pragma unroll
                    for (int in = 0; in < 4; in++)
                        #pragma unroll
                        for (int q = 0; q < 4; q++) acc[im][in][q] = 0.f;

                // 2 kt per batch: 16 LDG.32 front-batched, then 16 MMA
                #pragma unroll
                for (int ktb = 0; ktb < 2; ktb++) {
                    uint32_t a[2][2][4];
                    #pragma unroll
                    for (int kk = 0; kk < 2; kk++) {
                        const int h = (ktb * 2 + kk) * 16 + 2 * t;
                        #pragma unroll
                        for (int im = 0; im < 2; im++) {
                            const __half* r0 = ua + (size_t)(im * 16 + g) * DIN + h;
                            const __half* r1 = r0 + 8 * DIN;
                            a[kk][im][0] = *(const uint32_t*)(r0);
                            a[kk][im][1] = *(const uint32_t*)(r1);
                            a[kk][im][2] = *(const uint32_t*)(r0 + 8);
                            a[kk][im][3] = *(const uint32_t*)(r1 + 8);
                        }
                    }
                    #pragma unroll
                    for (int kk = 0; kk < 2; kk++) {
                        const int kt = ktb * 2 + kk;
                        #pragma unroll
                        for (int im = 0; im < 2; im++)
                            #pragma unroll
                            for (int in = 0; in < 4; in++)
                                asm volatile(
                                    "mma.sync.aligned.m16n8k16.row.col.f32.f16.f16.f32 "
                                    "{%0,%1,%2,%3}, {%4,%5,%6,%7}, {%8,%9}, {%0,%1,%2,%3};"
                                    : "+f"(acc[im][in][0]), "+f"(acc[im][in][1]),
                                      "+f"(acc[im][in][2]), "+f"(acc[im][in][3])
                                    : "r"(a[kk][im][0]), "r"(a[kk][im][1]),
                                      "r"(a[kk][im][2]), "r"(a[kk][im][3]),
                                      "r"(bfr[kt][in][0]), "r"(bfr[kt][in][1]));
                    }
                }

                // epilogue: D[m=l][n=p] -> stage[par][bw][p][t(=l)]  (CF)
                float* st = stage + (size_t)(par * 2 + bw) * PP * S2;
                #pragma unroll
                for (int im = 0; im < 2; im++) {
                    const int r0 = im * 16 + g;
                    #pragma unroll
                    for (int in = 0; in < 4; in++) {
                        const int c0 = wi * 32 + in * 8 + 2 * t;
                        st[(size_t)c0 * S2 + r0]           = acc[im][in][0];
                        st[(size_t)(c0 + 1) * S2 + r0]     = acc[im][in][1];
                        st[(size_t)c0 * S2 + r0 + 8]       = acc[im][in][2];
                        st[(size_t)(c0 + 1) * S2 + r0 + 8] = acc[im][in][3];
                    }
                }
            }
            BAR_SYNC(0, 256);   // lockstep handoff (carries memory fence)
        }
    } else {
        // ===================== CONSUMERS (4 warps) =========================
        const int ct = tid - 128;
        const int cb = ct >> 6;              // batch half (2 warps each)
        const int cp = ct & 63;              // p local
        const int b  = bpair * 2 + cb;
        const int p  = p0 + cp;
        const float d  = w_hh[(size_t)p * DS + p];
        const float bi = bias[p];
        float* ob = out + (size_t)b * DS * L_;
        const int wt = cp & 31, wr = cp >> 5;

        float x = 0.f;
        for (int it = 0; it <= NC; ++it) {
            if (it >= 1) {
                const int c   = it - 1;
                const int par = c & 1;
                float* st = stage + (size_t)(par * 2 + cb) * PP * S2;

                float upb[TC];
                #pragma unroll
                for (int t = 0; t < TC; t++)
                    upb[t] = st[(size_t)cp * S2 + t] + bi;

                #pragma unroll
                for (int t = 0; t < TC; t++) {
                    float z = fmaf(x, d, upb[t]);
                    float th;
                    asm("tanh.approx.f32 %0, %1;" : "=f"(th) : "f"(z));
                    float hx = 0.5f * x;
                    x = fmaf(0.5f, th, hx);
                    st[(size_t)cp * S2 + t] = x;     // in place for transpose
                }
                BAR_SYNC(5 + cb, 64);                // fence within b-half

                const int lc = c * TC;
                #pragma unroll
                for (int j = 0; j < TC; j++) {
                    const int pr = wr + j * 2;       // covers 0..63
                    ob[(size_t)(p0 + pr) * L_ + lc + wt] = st[(size_t)pr * S2 + wt];
                }
            }
            BAR_SYNC(0, 256);
        }
    }
}

extern "C" void kernel_launch(void* const* d_in, const int* in_sizes, int n_in,
                              void* d_out, int out_size) {
    const float* u    = (const float*)d_in[0];  // [32, 64, 2048]
    const float* w_in = (const float*)d_in[1];  // [1024, 64]
    const float* w_hh = (const float*)d_in[2];  // [1024, 1024]
    const float* bias = (const float*)d_in[3];  // [1024]
    float* out = (float*)d_out;                 // [32, 1024, 2048]

    dim3 gt(L_ / 32, B_);                       // 64 x 32 blocks
    transpose_u<<<gt, 256>>>(u);

    cudaFuncSetAttribute(esn_fused, cudaFuncAttributeMaxDynamicSharedMemorySize,
                         SMEM_TOTAL);
    dim3 g(DS / PP, B_ / 2);                    // 16 x 16 = 256 blocks, occ 2
    esn_fused<<<g, 256, SMEM_TOTAL>>>(w_in, w_hh, bias, out);
}

// round 8
// speedup vs baseline: 1.2063x; 1.2063x over previous
#include <cuda_runtime.h>
#include <cuda_fp16.h>
#include <cstdint>
#include <cstddef>

#define B_   32
#define DIN  64
#define DS   1024
#define L_   2048
#define PP   64      // p per block
#define TC   32      // timesteps per chunk
#define NC   (L_ / TC)
#define S2   35      // stage stride (floats): conflict-free scalar access
#define AS   70      // wsA/wsB row stride in halves (35 words, odd -> CF)

// dynamic smem per CTA (bytes)
#define STAGE_BYTES (2 * PP * S2 * 4)        // 17920  stage[par][p][t] fp32
#define WSA_BYTES   (2 * TC * AS * 2)        // 8960   wsA[par][l][h] fp16
#define WSB_BYTES   (PP * AS * 2)            // 8960   wsB[p][k] fp16
#define SMEM_TOTAL  (STAGE_BYTES + WSA_BYTES + WSB_BYTES)   // 35840 -> occ 4

#define BAR_SYNC(id, cnt) asm volatile("bar.sync %0, %1;" :: "r"(id), "r"(cnt) : "memory")

__global__ __launch_bounds__(128, 4)
void esn_fused(const float* __restrict__ u,
               const float* __restrict__ w_in,
               const float* __restrict__ w_hh,
               const float* __restrict__ bias,
               float* __restrict__ out) {
    extern __shared__ unsigned char smem_raw[];
    float*  stage = (float*)smem_raw;                                // [2][PP][S2]
    __half* wsA   = (__half*)(smem_raw + STAGE_BYTES);               // [2][TC][AS]
    __half* wsB   = (__half*)(smem_raw + STAGE_BYTES + WSA_BYTES);   // [PP][AS]

    const int tid = threadIdx.x;
    const int p0  = blockIdx.x * PP;
    const int b   = blockIdx.y;

    // wsB fill: wsB[p][k] = fp16(w_in[p0+p][k])
    for (int i = tid; i < PP * DIN; i += 128) {
        int p = i >> 6, k = i & 63;
        wsB[p * AS + k] = __float2half_rn(w_in[(size_t)(p0 + p) * DIN + k]);
    }
    __syncthreads();

    const float* ub = u + (size_t)b * DIN * L_;

    // prefetch chunk 0: i = tid + 128j -> h = i>>5, l = i&31 (coalesced per warp)
    float uv[16];
    #pragma unroll
    for (int j = 0; j < 16; j++) {
        int i = tid + j * 128;
        int h = i >> 5, l = i & 31;
        uv[j] = ub[(size_t)h * L_ + l];
    }

    const int warp = tid >> 5;
    const bool is_prod = (warp < 2);

    // ---- producer-only state (warps 0,1) ----
    const int lane = tid & 31;
    const int g = lane >> 2, t = lane & 3;
    const int wi = warp & 1;                 // 32-wide p tile
    uint32_t bfr[4][4][2];                   // chunk-invariant B fragments
    if (is_prod) {
        #pragma unroll
        for (int kt = 0; kt < 4; kt++)
            #pragma unroll
            for (int in = 0; in < 4; in++) {
                const __half* wp = wsB + (size_t)(wi * 32 + in * 8 + g) * AS + kt * 16 + 2 * t;
                bfr[kt][in][0] = *(const uint32_t*)(wp);
                bfr[kt][in][1] = *(const uint32_t*)(wp + 8);
            }
    }

    // ---- consumer-only state (warps 2,3) ----
    const int cp = tid - 64;                 // 0..63 for consumers
    float d = 0.f, bi = 0.f;
    if (!is_prod) {
        const int p = p0 + cp;
        d  = w_hh[(size_t)p * DS + p];
        bi = bias[p];
    }
    float* ob = out + (size_t)b * DS * L_;
    const int wt = cp & 31, wr = cp >> 5;
    float x = 0.f;

    for (int it = 0; it <= NC; ++it) {
        const int par = it & 1;

        // all 128 threads: store prefetched chunk to wsA[par][l][h]
        if (it < NC) {
            #pragma unroll
            for (int j = 0; j < 16; j++) {
                int i = tid + j * 128;
                int h = i >> 5, l = i & 31;
                wsA[((size_t)(par * TC) + l) * AS + h] = __float2half_rn(uv[j]);
            }
        }
        BAR_SYNC(0, 128);    // wsA[par] visible; stage[par] free (cons done last it)

        // all threads: prefetch next chunk (latency hidden across the iteration)
        if (it + 1 < NC) {
            const int lc = (it + 1) * TC;
            #pragma unroll
            for (int j = 0; j < 16; j++) {
                int i = tid + j * 128;
                int h = i >> 5, l = i & 31;
                uv[j] = ub[(size_t)h * L_ + lc + l];
            }
        }

        if (is_prod) {
            if (it < NC) {
                float acc[2][4][4];
                #pragma unroll
                for (int im = 0; im < 2; im++)
                    #pragma unroll
                    for (int in = 0; in < 4; in++)
                        #pragma unroll
                        for (int q = 0; q < 4; q++) acc[im][in][q] = 0.f;

                const __half* wa = wsA + (size_t)(par * TC) * AS;
                #pragma unroll
                for (int kt = 0; kt < 4; kt++) {
                    uint32_t a[2][4];
                    #pragma unroll
                    for (int im = 0; im < 2; im++) {
                        const __half* r0p = wa + (size_t)(im * 16 + g) * AS + kt * 16 + 2 * t;
                        const __half* r1p = r0p + 8 * AS;
                        a[im][0] = *(const uint32_t*)(r0p);
                        a[im][1] = *(const uint32_t*)(r1p);
                        a[im][2] = *(const uint32_t*)(r0p + 8);
                        a[im][3] = *(const uint32_t*)(r1p + 8);
                    }
                    #pragma unroll
                    for (int im = 0; im < 2; im++)
                        #pragma unroll
                        for (int in = 0; in < 4; in++)
                            asm volatile(
                                "mma.sync.aligned.m16n8k16.row.col.f32.f16.f16.f32 "
                                "{%0,%1,%2,%3}, {%4,%5,%6,%7}, {%8,%9}, {%0,%1,%2,%3};"
                                : "+f"(acc[im][in][0]), "+f"(acc[im][in][1]),
                                  "+f"(acc[im][in][2]), "+f"(acc[im][in][3])
                                : "r"(a[im][0]), "r"(a[im][1]), "r"(a[im][2]), "r"(a[im][3]),
                                  "r"(bfr[kt][in][0]), "r"(bfr[kt][in][1]));
                }

                // epilogue: D[m=l][n=p] -> stage[par][p][t(=l)]
                float* st = stage + (size_t)par * PP * S2;
                #pragma unroll
                for (int im = 0; im < 2; im++) {
                    const int r0 = im * 16 + g;
                    #pragma unroll
                    for (int in = 0; in < 4; in++) {
                        const int c0 = wi * 32 + in * 8 + 2 * t;
                        st[(size_t)c0 * S2 + r0]           = acc[im][in][0];
                        st[(size_t)(c0 + 1) * S2 + r0]     = acc[im][in][1];
                        st[(size_t)c0 * S2 + r0 + 8]       = acc[im][in][2];
                        st[(size_t)(c0 + 1) * S2 + r0 + 8] = acc[im][in][3];
                    }
                }
            }
        } else {
            if (it >= 1) {
                const int c = it - 1;
                float* st = stage + (size_t)(c & 1) * PP * S2;

                float upb[TC];
                #pragma unroll
                for (int t2 = 0; t2 < TC; t2++)
                    upb[t2] = st[(size_t)cp * S2 + t2] + bi;

                #pragma unroll
                for (int t2 = 0; t2 < TC; t2++) {
                    float z = fmaf(x, d, upb[t2]);
                    float th;
                    asm("tanh.approx.f32 %0, %1;" : "=f"(th) : "f"(z));
                    float hx = 0.5f * x;
                    x = fmaf(0.5f, th, hx);
                    st[(size_t)cp * S2 + t2] = x;    // in place for transpose
                }
                BAR_SYNC(1, 64);                     // both consumer warps fence

                const int lc = c * TC;
                #pragma unroll
                for (int j = 0; j < TC; j++) {
                    const int pr = wr + j * 2;       // covers 0..63
                    ob[(size_t)(p0 + pr) * L_ + lc + wt] = st[(size_t)pr * S2 + wt];
                }
            }
        }
        BAR_SYNC(0, 128);   // handoff: swap parities (carries memory fence)
    }
}

extern "C" void kernel_launch(void* const* d_in, const int* in_sizes, int n_in,
                              void* d_out, int out_size) {
    const float* u    = (const float*)d_in[0];  // [32, 64, 2048]
    const float* w_in = (const float*)d_in[1];  // [1024, 64]
    const float* w_hh = (const float*)d_in[2];  // [1024, 1024]
    const float* bias = (const float*)d_in[3];  // [1024]
    float* out = (float*)d_out;                 // [32, 1024, 2048]

    cudaFuncSetAttribute(esn_fused, cudaFuncAttributeMaxDynamicSharedMemorySize,
                         SMEM_TOTAL);
    dim3 g(DS / PP, B_);                        // 16 x 32 = 512 blocks, occ 4
    esn_fused<<<g, 128, SMEM_TOTAL>>>(u, w_in, w_hh, bias, out);
}

// round 9
// speedup vs baseline: 1.2922x; 1.0713x over previous
#include <cuda_runtime.h>
#include <cuda_fp16.h>
#include <cstdint>
#include <cstddef>

#define B_   32
#define DIN  64
#define DS   1024
#define L_   2048
#define PP   64      // p per block
#define TC   32      // timesteps per chunk
#define NC   (L_ / TC)
#define S2   36      // stage stride (floats): 16B-aligned rows, CF for .128
#define AS   72      // wsA/wsB row stride in halves: 144B rows, 16B-aligned

// dynamic smem per CTA (bytes)
#define STAGE_BYTES (2 * PP * S2 * 4)        // 18432  stage[par][p][t] fp32
#define WSA_BYTES   (TC * AS * 2)            // 4608   wsA[l][h] fp16 (single buf)
#define WSB_BYTES   (PP * AS * 2)            // 9216   wsB[p][k] fp16
#define SMEM_TOTAL  (STAGE_BYTES + WSA_BYTES + WSB_BYTES)   // 32256 -> occ 3

#define BAR_SYNC(id, cnt) asm volatile("bar.sync %0, %1;" :: "r"(id), "r"(cnt) : "memory")
// ids: 0 = all 192, 1 = producers 128, 2 = consumers 64

__device__ __forceinline__ uint32_t sptr(const void* p) {
    return (uint32_t)__cvta_generic_to_shared(p);
}

__global__ __launch_bounds__(192, 3)
void esn_fused(const float* __restrict__ u,
               const float* __restrict__ w_in,
               const float* __restrict__ w_hh,
               const float* __restrict__ bias,
               float* __restrict__ out) {
    extern __shared__ unsigned char smem_raw[];
    float*  stage = (float*)smem_raw;                                // [2][PP][S2]
    __half* wsA   = (__half*)(smem_raw + STAGE_BYTES);               // [TC][AS]
    __half* wsB   = (__half*)(smem_raw + STAGE_BYTES + WSA_BYTES);   // [PP][AS]

    const int tid = threadIdx.x;
    const int p0  = blockIdx.x * PP;
    const int b   = blockIdx.y;

    // wsB fill: wsB[p][k] = fp16(w_in[p0+p][k])   (one-time)
    for (int i = tid; i < PP * DIN; i += 192) {
        int p = i >> 6, k = i & 63;
        wsB[p * AS + k] = __float2half_rn(w_in[(size_t)(p0 + p) * DIN + k]);
    }
    __syncthreads();

    const float* ub = u + (size_t)b * DIN * L_;

    if (tid < 128) {
        // ===================== PRODUCERS (4 warps, m16 x n32) ==============
        const int warp = tid >> 5;
        const int mh   = warp >> 1;          // l-half (16 rows)
        const int nh   = warp & 1;           // p-half (32 cols)
        const int lane = tid & 31;
        const int g = lane >> 2, t = lane & 3;

        // chunk-invariant B fragments: 4 kt x 4 n-tiles x 2 regs = 32
        uint32_t bfr[4][4][2];
        #pragma unroll
        for (int kt = 0; kt < 4; kt++)
            #pragma unroll
            for (int in = 0; in < 4; in++) {
                const __half* wp = wsB + (size_t)(nh * 32 + in * 8 + g) * AS + kt * 16 + 2 * t;
                bfr[kt][in][0] = *(const uint32_t*)(wp);
                bfr[kt][in][1] = *(const uint32_t*)(wp + 8);
            }

        // fill indexing: l = tid&31, hg = tid>>5; h0 = (hg + 4*pass)*8
        const int fl = tid & 31;
        const int hg = tid >> 5;

        // ldmatrix per-lane row address (within wsA): row = mh*16 + (lane&15),
        // + 16B half-select (lane>>4)
        const uint32_t lm_base = sptr(wsA) + (uint32_t)(mh * 16 + (lane & 15)) * (AS * 2)
                               + ((lane >> 4) & 1) * 16;

        // prefetch chunk 0
        float uv[16];
        #pragma unroll
        for (int pass = 0; pass < 2; pass++) {
            const int h0 = (hg + 4 * pass) * 8;
            #pragma unroll
            for (int j = 0; j < 8; j++)
                uv[pass * 8 + j] = ub[(size_t)(h0 + j) * L_ + fl];
        }

        for (int it = 0; it <= NC; ++it) {
            if (it < NC) {
                const int par = it & 1;

                // store prefetched chunk to wsA[l][h] via STS.128 (CF)
                #pragma unroll
                for (int pass = 0; pass < 2; pass++) {
                    const int h0 = (hg + 4 * pass) * 8;
                    __half2 pk[4];
                    #pragma unroll
                    for (int j = 0; j < 4; j++)
                        pk[j] = __floats2half2_rn(uv[pass * 8 + 2 * j],
                                                  uv[pass * 8 + 2 * j + 1]);
                    *(uint4*)(wsA + (size_t)fl * AS + h0) = *(uint4*)pk;
                }
                BAR_SYNC(1, 128);

                // prefetch next chunk (hidden under MMA + epilogue)
                if (it + 1 < NC) {
                    const int lc = (it + 1) * TC;
                    #pragma unroll
                    for (int pass = 0; pass < 2; pass++) {
                        const int h0 = (hg + 4 * pass) * 8;
                        #pragma unroll
                        for (int j = 0; j < 8; j++)
                            uv[pass * 8 + j] = ub[(size_t)(h0 + j) * L_ + lc + fl];
                    }
                }

                float acc[4][4];
                #pragma unroll
                for (int in = 0; in < 4; in++)
                    #pragma unroll
                    for (int q = 0; q < 4; q++) acc[in][q] = 0.f;

                // 2 kt per batch: 2 LDSM.x4 then 8 MMAs
                #pragma unroll
                for (int ktb = 0; ktb < 2; ktb++) {
                    uint32_t a[2][4];
                    #pragma unroll
                    for (int kk = 0; kk < 2; kk++) {
                        const uint32_t addr = lm_base + (ktb * 2 + kk) * 32;
                        asm volatile(
                            "ldmatrix.sync.aligned.m8n8.x4.shared.b16 "
                            "{%0,%1,%2,%3}, [%4];"
                            : "=r"(a[kk][0]), "=r"(a[kk][1]),
                              "=r"(a[kk][2]), "=r"(a[kk][3])
                            : "r"(addr));
                    }
                    #pragma unroll
                    for (int kk = 0; kk < 2; kk++) {
                        const int kt = ktb * 2 + kk;
                        #pragma unroll
                        for (int in = 0; in < 4; in++)
                            asm volatile(
                                "mma.sync.aligned.m16n8k16.row.col.f32.f16.f16.f32 "
                                "{%0,%1,%2,%3}, {%4,%5,%6,%7}, {%8,%9}, {%0,%1,%2,%3};"
                                : "+f"(acc[in][0]), "+f"(acc[in][1]),
                                  "+f"(acc[in][2]), "+f"(acc[in][3])
                                : "r"(a[kk][0]), "r"(a[kk][1]),
                                  "r"(a[kk][2]), "r"(a[kk][3]),
                                  "r"(bfr[kt][in][0]), "r"(bfr[kt][in][1]));
                    }
                }

                // epilogue: D[m=l][n=p] -> stage[par][p][t(=l)]  (CF, bank 8t+g)
                float* st = stage + (size_t)par * PP * S2;
                const int r0 = mh * 16 + g;
                #pragma unroll
                for (int in = 0; in < 4; in++) {
                    const int c0 = nh * 32 + in * 8 + 2 * t;
                    st[(size_t)c0 * S2 + r0]           = acc[in][0];
                    st[(size_t)(c0 + 1) * S2 + r0]     = acc[in][1];
                    st[(size_t)c0 * S2 + r0 + 8]       = acc[in][2];
                    st[(size_t)(c0 + 1) * S2 + r0 + 8] = acc[in][3];
                }
            }
            BAR_SYNC(0, 192);   // lockstep handoff (carries memory fence)
        }
    } else {
        // ===================== CONSUMERS (2 warps) =========================
        const int cp   = tid - 128;          // 0..63 -> p local (= chain id)
        const int lane = tid & 31;
        const int cw   = (tid - 128) >> 5;   // consumer warp 0/1
        const int hi   = lane >> 4;          // p-row parity for transpose
        const int lt   = lane & 15;          // t-pair index
        const int p    = p0 + cp;
        const float d  = w_hh[(size_t)p * DS + p];
        const float bi = bias[p];
        float* ob = out + (size_t)b * DS * L_;

        float x = 0.f;
        for (int it = 0; it <= NC; ++it) {
            if (it >= 1) {
                const int c = it - 1;
                float* st = stage + (size_t)(c & 1) * PP * S2;
                float* row = st + (size_t)cp * S2;

                // vector chain-input loads (LDS.128, CF)
                float upb[TC];
                #pragma unroll
                for (int k = 0; k < 8; k++) {
                    float4 v = *(const float4*)(row + 4 * k);
                    upb[4 * k]     = v.x + bi;
                    upb[4 * k + 1] = v.y + bi;
                    upb[4 * k + 2] = v.z + bi;
                    upb[4 * k + 3] = v.w + bi;
                }

                // serial chain; pack 4 x values -> STS.128
                #pragma unroll
                for (int kb = 0; kb < 8; kb++) {
                    float xv[4];
                    #pragma unroll
                    for (int q = 0; q < 4; q++) {
                        float z = fmaf(x, d, upb[kb * 4 + q]);
                        float th;
                        asm("tanh.approx.f32 %0, %1;" : "=f"(th) : "f"(z));
                        x = fmaf(0.5f, th, 0.5f * x);
                        xv[q] = x;
                    }
                    *(float4*)(row + 4 * kb) = make_float4(xv[0], xv[1], xv[2], xv[3]);
                }
                BAR_SYNC(2, 64);                 // x visible to both cons warps

                // transpose out: LDS.64 + STG.64 (CF / coalesced pairs)
                const int lc = c * TC;
                #pragma unroll
                for (int j = 0; j < 16; j++) {
                    const int pr = cw * 32 + 2 * j + hi;   // covers 0..63
                    float2 v = *(const float2*)(st + (size_t)pr * S2 + 2 * lt);
                    *(float2*)(ob + (size_t)(p0 + pr) * L_ + lc + 2 * lt) = v;
                }
            }
            BAR_SYNC(0, 192);
        }
    }
}

extern "C" void kernel_launch(void* const* d_in, const int* in_sizes, int n_in,
                              void* d_out, int out_size) {
    const float* u    = (const float*)d_in[0];  // [32, 64, 2048]
    const float* w_in = (const float*)d_in[1];  // [1024, 64]
    const float* w_hh = (const float*)d_in[2];  // [1024, 1024]
    const float* bias = (const float*)d_in[3];  // [1024]
    float* out = (float*)d_out;                 // [32, 1024, 2048]

    cudaFuncSetAttribute(esn_fused, cudaFuncAttributeMaxDynamicSharedMemorySize,
                         SMEM_TOTAL);
    dim3 g(DS / PP, B_);                        // 16 x 32 = 512 blocks, occ 3
    esn_fused<<<g, 192, SMEM_TOTAL>>>(u, w_in, w_hh, bias, out);
}

// round 10
// speedup vs baseline: 2.1478x; 1.6620x over previous
#include <cuda_runtime.h>
#include <cuda_fp16.h>
#include <cstdint>
#include <cstddef>

#define B_   32
#define DIN  64
#define DS   1024
#define L_   2048
#define PP   128     // p per block
#define TC   32      // timesteps per chunk
#define NC   (L_ / TC)
#define S2   36      // stage stride (floats), 16B-aligned rows
#define AS   72      // wsA row stride in halves (R9-validated ldmatrix layout)
#define NSLOT 3

// pre-transposed input: g_ut[b][l][h] fp16 (8 MB), written by pre-kernel
__device__ __half g_ut[(size_t)B_ * L_ * DIN];

// dynamic smem layout (bytes)
#define STAGE_BYTES (NSLOT * PP * S2 * 4)    // 55296  stage[slot][p][t] fp32
#define WSA_BYTES   (2 * TC * AS * 2)        // 9216   wsA[par][l][h] fp16
#define WSB_BYTES   (PP * AS * 2)            // 18432  wsB[p][k] fp16
#define SMEM_TOTAL  (STAGE_BYTES + WSA_BYTES + WSB_BYTES)   // 82944 -> occ 2

#define BAR_SYNC(id, cnt) asm volatile("bar.sync %0, %1;" :: "r"(id), "r"(cnt) : "memory")
// ids: 0 = all 320 (init), 1+s = FULL_PC[s] (256), 4+s = FULL_CW[s] (192),
//      10 = producer-internal fill barrier (128)

__device__ __forceinline__ uint32_t sptr(const void* p) {
    return (uint32_t)__cvta_generic_to_shared(p);
}

// ---------------------------------------------------------------------------
// Pre-kernel: g_ut[b][l][h] = fp16(u[b][h][l])   (validated in R7)
// ---------------------------------------------------------------------------
__global__ __launch_bounds__(256)
void transpose_u(const float* __restrict__ u) {
    __shared__ float ts[DIN][33];
    const int b  = blockIdx.y;
    const int lc = blockIdx.x * 32;
    const int tid = threadIdx.x;
    const float* ub = u + (size_t)b * DIN * L_;

    #pragma unroll
    for (int k = 0; k < 8; k++) {
        int idx = tid + k * 256;
        int h = idx >> 5, l = idx & 31;
        ts[h][l] = ub[(size_t)h * L_ + lc + l];
    }
    __syncthreads();

    const int l  = tid >> 3;
    const int h0 = (tid & 7) * 8;
    __half2 p[4];
    #pragma unroll
    for (int j = 0; j < 4; j++)
        p[j] = __halves2half2(__float2half_rn(ts[h0 + 2 * j][l]),
                              __float2half_rn(ts[h0 + 2 * j + 1][l]));
    *(uint4*)(g_ut + ((size_t)b * L_ + lc + l) * DIN + h0) = *(uint4*)p;
}

// ---------------------------------------------------------------------------
// Fused: 4 P warps (MMA) -> 3-slot ring -> 4 C warps (chain) -> 2 W warps (STG)
// ---------------------------------------------------------------------------
__global__ __launch_bounds__(320, 2)
void esn_fused(const float* __restrict__ w_in,
               const float* __restrict__ w_hh,
               const float* __restrict__ bias,
               float* __restrict__ out) {
    extern __shared__ unsigned char smem_raw[];
    float*  stage = (float*)smem_raw;                                // [3][PP][S2]
    __half* wsA   = (__half*)(smem_raw + STAGE_BYTES);               // [2][TC][AS]
    __half* wsB   = (__half*)(smem_raw + STAGE_BYTES + WSA_BYTES);   // [PP][AS]

    const int tid = threadIdx.x;
    const int p0  = blockIdx.x * PP;
    const int b   = blockIdx.y;

    // wsB fill: wsB[p][k] = fp16(w_in[p0+p][k])
    for (int i = tid; i < PP * DIN; i += 320) {
        int p = i >> 6, k = i & 63;
        wsB[p * AS + k] = __float2half_rn(w_in[(size_t)(p0 + p) * DIN + k]);
    }
    __syncthreads();

    if (tid < 128) {
        // ===================== PRODUCERS (4 warps, m32 x n32) ==============
        const int warp = tid >> 5;           // n-tile: p cols [warp*32, +32)
        const int lane = tid & 31;
        const int g = lane >> 2, t = lane & 3;
        const __half* ut = g_ut + (size_t)b * L_ * DIN;

        // chunk-invariant B fragments: 4 kt x 4 n8 x 2 regs = 32
        uint32_t bfr[4][4][2];
        #pragma unroll
        for (int kt = 0; kt < 4; kt++)
            #pragma unroll
            for (int in = 0; in < 4; in++) {
                const __half* wp = wsB + (size_t)(warp * 32 + in * 8 + g) * AS + kt * 16 + 2 * t;
                bfr[kt][in][0] = *(const uint32_t*)(wp);
                bfr[kt][in][1] = *(const uint32_t*)(wp + 8);
            }

        // cp.async fill: 256 x 16B blocks per chunk; thread does blocks tid, tid+128
        const uint32_t wsa_base = sptr(wsA);
        #define ISSUE_FILL(c)                                                          \
        do {                                                                           \
            const int par_ = (c) & 1;                                                  \
            const __half* src_ = ut + (size_t)(c) * TC * DIN;                          \
            _Pragma("unroll")                                                          \
            for (int q_ = 0; q_ < 2; q_++) {                                           \
                int i_ = tid + q_ * 128;                                               \
                uint32_t dst_ = wsa_base + (uint32_t)(par_ * TC * AS + (i_ >> 3) * AS  \
                                + (i_ & 7) * 8) * 2;                                   \
                asm volatile("cp.async.cg.shared.global [%0], [%1], 16;"               \
                             :: "r"(dst_), "l"(src_ + i_ * 8));                        \
            }                                                                          \
        } while (0)

        // ldmatrix lane address within a wsA buffer (R9-validated pattern)
        const uint32_t lm_off = (uint32_t)((lane & 15) * AS) * 2 + ((lane >> 4) & 1) * 16;

        ISSUE_FILL(0);
        asm volatile("cp.async.commit_group;");

        for (int it = 0; it < NC; ++it) {
            const int par = it & 1;
            if (it + 1 < NC) ISSUE_FILL(it + 1);
            asm volatile("cp.async.commit_group;");
            asm volatile("cp.async.wait_group 1;");
            BAR_SYNC(10, 128);               // all fills for chunk `it` visible

            float acc[2][4][4];
            #pragma unroll
            for (int im = 0; im < 2; im++)
                #pragma unroll
                for (int in = 0; in < 4; in++)
                    #pragma unroll
                    for (int q = 0; q < 4; q++) acc[im][in][q] = 0.f;

            const uint32_t abase = wsa_base + (uint32_t)(par * TC * AS) * 2 + lm_off;
            #pragma unroll
            for (int kt = 0; kt < 4; kt++) {
                uint32_t a[2][4];
                #pragma unroll
                for (int im = 0; im < 2; im++) {
                    const uint32_t addr = abase + (uint32_t)(im * 16 * AS) * 2 + kt * 32;
                    asm volatile(
                        "ldmatrix.sync.aligned.m8n8.x4.shared.b16 {%0,%1,%2,%3}, [%4];"
                        : "=r"(a[im][0]), "=r"(a[im][1]), "=r"(a[im][2]), "=r"(a[im][3])
                        : "r"(addr));
                }
                #pragma unroll
                for (int im = 0; im < 2; im++)
                    #pragma unroll
                    for (int in = 0; in < 4; in++)
                        asm volatile(
                            "mma.sync.aligned.m16n8k16.row.col.f32.f16.f16.f32 "
                            "{%0,%1,%2,%3}, {%4,%5,%6,%7}, {%8,%9}, {%0,%1,%2,%3};"
                            : "+f"(acc[im][in][0]), "+f"(acc[im][in][1]),
                              "+f"(acc[im][in][2]), "+f"(acc[im][in][3])
                            : "r"(a[im][0]), "r"(a[im][1]), "r"(a[im][2]), "r"(a[im][3]),
                              "r"(bfr[kt][in][0]), "r"(bfr[kt][in][1]));
            }

            // epilogue: D[m=l][n=p] -> stage[slot][p][t(=l)]  (banks 8t+g, CF)
            float* st = stage + (size_t)(it % NSLOT) * PP * S2;
            #pragma unroll
            for (int im = 0; im < 2; im++) {
                const int r0 = im * 16 + g;
                #pragma unroll
                for (int in = 0; in < 4; in++) {
                    const int c0 = warp * 32 + in * 8 + 2 * t;
                    st[(size_t)c0 * S2 + r0]           = acc[im][in][0];
                    st[(size_t)(c0 + 1) * S2 + r0]     = acc[im][in][1];
                    st[(size_t)c0 * S2 + r0 + 8]       = acc[im][in][2];
                    st[(size_t)(c0 + 1) * S2 + r0 + 8] = acc[im][in][3];
                }
            }
            BAR_SYNC(1 + it % NSLOT, 256);   // FULL_PC rendezvous (fence)
        }
    } else if (tid < 256) {
        // ===================== CHAIN WARPS (4, 128 chains) =================
        const int cp = tid - 128;            // p local
        const int p  = p0 + cp;
        const float d  = w_hh[(size_t)p * DS + p];
        const float bi = bias[p];

        float x = 0.f;
        for (int c = 0; c < NC; ++c) {
            const int s = c % NSLOT;
            BAR_SYNC(1 + s, 256);            // wait pre[c]
            float* row = stage + (size_t)s * PP * S2 + (size_t)cp * S2;

            float upb[TC];
            #pragma unroll
            for (int k = 0; k < 8; k++) {
                float4 v = *(const float4*)(row + 4 * k);
                upb[4 * k]     = v.x + bi;
                upb[4 * k + 1] = v.y + bi;
                upb[4 * k + 2] = v.z + bi;
                upb[4 * k + 3] = v.w + bi;
            }
            #pragma unroll
            for (int kb = 0; kb < 8; kb++) {
                float xv[4];
                #pragma unroll
                for (int q = 0; q < 4; q++) {
                    float z = fmaf(x, d, upb[kb * 4 + q]);
                    float th;
                    asm("tanh.approx.f32 %0, %1;" : "=f"(th) : "f"(z));
                    x = fmaf(0.5f, th, 0.5f * x);
                    xv[q] = x;
                }
                *(float4*)(row + 4 * kb) = make_float4(xv[0], xv[1], xv[2], xv[3]);
            }
            BAR_SYNC(4 + s, 192);            // FULL_CW rendezvous (fence)
        }
    } else {
        // ===================== WRITER WARPS (2) ============================
        const int wt   = tid - 256;          // 0..63
        const int w    = wt >> 5;            // writer warp
        const int lane = wt & 31;
        const int rsub = lane >> 3;          // row within group of 4
        const int c4   = 4 * (lane & 7);     // t offset (float4)
        float* ob = out + (size_t)b * DS * L_;

        for (int c = 0; c < NC; ++c) {
            const int s = c % NSLOT;
            BAR_SYNC(4 + s, 192);            // wait x[c]
            const float* st = stage + (size_t)s * PP * S2;
            const int lc = c * TC;
            #pragma unroll
            for (int j = 0; j < 16; j++) {
                const int pr = w * 64 + j * 4 + rsub;     // covers 0..127
                float4 v = *(const float4*)(st + (size_t)pr * S2 + c4);
                __stcs((float4*)(ob + (size_t)(p0 + pr) * L_ + lc + c4), v);
            }
        }
    }
}

extern "C" void kernel_launch(void* const* d_in, const int* in_sizes, int n_in,
                              void* d_out, int out_size) {
    const float* u    = (const float*)d_in[0];  // [32, 64, 2048]
    const float* w_in = (const float*)d_in[1];  // [1024, 64]
    const float* w_hh = (const float*)d_in[2];  // [1024, 1024]
    const float* bias = (const float*)d_in[3];  // [1024]
    float* out = (float*)d_out;                 // [32, 1024, 2048]

    dim3 gt(L_ / 32, B_);
    transpose_u<<<gt, 256>>>(u);

    cudaFuncSetAttribute(esn_fused, cudaFuncAttributeMaxDynamicSharedMemorySize,
                         SMEM_TOTAL);
    dim3 g(DS / PP, B_);                        // 8 x 32 = 256 blocks, occ 2
    esn_fused<<<g, 320, SMEM_TOTAL>>>(w_in, w_hh, bias, out);
}